// round 11
// baseline (speedup 1.0000x reference)
#include <cuda_runtime.h>

#define VDIM 5000
#define MDIM 256
#define NCH 63        // split-K chunks: 63*80 = 5040 >= 5000
#define CHUNK 80
#define LMB 0.001f
#define NITER 2

// ---------------------------------------------------------------------------
// Device scratch (allocation-free rule), 16B-aligned
// ---------------------------------------------------------------------------
__device__ __align__(16) float g_part[2 * NCH * 4 * 64 * 64];
__device__ __align__(16) float g_A[64 * 256], g_T[64 * 256];
__device__ __align__(16) float g_S[4096];
__device__ __align__(16) float g_AAt[4096], g_TA[4096];
__device__ __align__(16) float g_Qm[4096], g_Sinv[4096], g_AAti[4096];
__device__ __align__(16) float g_QtP[4096], g_QtQ[4096], g_U1[4096];
__device__ __align__(16) float g_L3[4096], g_L4[4096];
__device__ __align__(16) float g_R1[4096], g_R2[4096], g_R4[4096];
__device__ __align__(16) float g_X0[4096], g_X[4096];
__device__ __align__(16) float g_M1[4096], g_M2[4096], g_M4[4096];

// ---------------------------------------------------------------------------
// Big GEMMs: A = tx[64,V] @ fx[V,256], T = ty @ fy.  4x4 microtile, split-K.
// ---------------------------------------------------------------------------
__global__ void __launch_bounds__(256) big_gemm(
        const float* __restrict__ fx, const float* __restrict__ fy,
        const float* __restrict__ tx, const float* __restrict__ ty) {
    int ch = blockIdx.x, ct = blockIdx.y, mz = blockIdx.z;
    const float* f = mz ? fy : fx;
    const float* t = mz ? ty : tx;

    __shared__ __align__(16) float tsT[16][68];
    __shared__ __align__(16) float fs[16][64];

    int tid = threadIdx.x;
    int r0 = (tid >> 4) * 4;
    int c0 = (tid & 15) * 4;

    float acc[4][4];
#pragma unroll
    for (int i = 0; i < 4; i++)
#pragma unroll
        for (int j = 0; j < 4; j++) acc[i][j] = 0.f;

    int lr = tid >> 2, lkq = (tid & 3) * 4;
    int fkk = tid >> 4, fcb = (tid & 15) * 4;

    int k0 = ch * CHUNK;
    for (int sub = 0; sub < CHUNK / 16; ++sub) {
        int kb = k0 + sub * 16;
#pragma unroll
        for (int q = 0; q < 4; q++) {
            int k = kb + lkq + q;
            tsT[lkq + q][lr] = (k < VDIM) ? t[lr * VDIM + k] : 0.f;
        }
        {
            int k = kb + fkk;
            float4 fv = make_float4(0.f, 0.f, 0.f, 0.f);
            if (k < VDIM) fv = *(const float4*)&f[k * MDIM + ct * 64 + fcb];
            *(float4*)&fs[fkk][fcb] = fv;
        }
        __syncthreads();
#pragma unroll
        for (int kk = 0; kk < 16; kk++) {
            float4 av = *(const float4*)&tsT[kk][r0];
            float4 bv = *(const float4*)&fs[kk][c0];
            float a[4] = {av.x, av.y, av.z, av.w};
            float b[4] = {bv.x, bv.y, bv.z, bv.w};
#pragma unroll
            for (int i = 0; i < 4; i++)
#pragma unroll
                for (int j = 0; j < 4; j++) acc[i][j] += a[i] * b[j];
        }
        __syncthreads();
    }
    size_t base = (((size_t)mz * NCH + ch) * 4 + ct) * 4096;
#pragma unroll
    for (int i = 0; i < 4; i++)
        *(float4*)&g_part[base + (size_t)(r0 + i) * 64 + c0] =
            make_float4(acc[i][0], acc[i][1], acc[i][2], acc[i][3]);
}

// ---------------------------------------------------------------------------
// Named barrier for a 512-thread half-block
// ---------------------------------------------------------------------------
__device__ __forceinline__ void half_bar(int id) {
    asm volatile("bar.sync %0, %1;" :: "r"(id), "r"(512) : "memory");
}

// ---------------------------------------------------------------------------
// Register-resident Gauss-Jordan 64x64 inversion, 512 threads (no pivoting).
// lt in [0,512): r = lt&63 (row), g = lt>>6 (8 col groups of 16).
// Pivot row/col double-buffered in shared -> 1 named barrier per pivot.
// Deferred normalization. Loop unrolled -> publish indices static.
// ---------------------------------------------------------------------------
__device__ __noinline__ void gj_inv512(const float* __restrict__ Ain,
                                       float* __restrict__ Aout,
                                       int barid, int lt,
                                       float (*pr)[128], float (*fc)[64]) {
    int r = lt & 63, g = lt >> 6, j0 = g * 16;
    float a[16];
#pragma unroll
    for (int jj = 0; jj < 16; jj++) {
        int j = j0 + jj;
        a[jj] = (j < 64) ? Ain[r * 64 + j] : ((j - 64 == r) ? 1.f : 0.f);
    }
    if (g == 0) fc[0][r] = a[0];
    if (r == 0) {
#pragma unroll
        for (int jj = 0; jj < 16; jj++) pr[0][j0 + jj] = a[jj];
    }
    half_bar(barid);
    float mydiag = 1.f;
#pragma unroll
    for (int p = 0; p < 64; p++) {
        const int cur = p & 1, nxt = cur ^ 1;
        float apiv = fc[cur][p];
        float scale = __fdividef(fc[cur][r], apiv);
        if (r == p) mydiag = apiv;
        if (r != p) {
#pragma unroll
            for (int jj = 0; jj < 16; jj++) a[jj] -= scale * pr[cur][j0 + jj];
        }
        if (p < 63) {
            const int q = p + 1;
            if (g == (q >> 4)) fc[nxt][r] = a[q & 15];   // static under unroll
            if (r == q) {
#pragma unroll
                for (int jj = 0; jj < 16; jj++) pr[nxt][j0 + jj] = a[jj];
            }
        }
        half_bar(barid);
    }
    if (g >= 4) {
        float dinv = 1.f / mydiag;
#pragma unroll
        for (int jj = 0; jj < 16; jj++)
            Aout[r * 64 + (j0 - 64) + jj] = a[jj] * dinv;
    }
}

// ---------------------------------------------------------------------------
// 512-thread helpers: full 64x64 outputs, 2-row x 4-col tiles
//   pair = lt>>4 (32 row pairs), c0 = (lt&15)*4
// ---------------------------------------------------------------------------
__device__ void dot_nt256_512(const float* __restrict__ L, const float* __restrict__ R,
                              float* __restrict__ C, int lt) {
    int r = (lt >> 4) * 2, c0 = (lt & 15) * 4;
    float s[2][4];
#pragma unroll
    for (int i = 0; i < 2; i++)
#pragma unroll
        for (int j = 0; j < 4; j++) s[i][j] = 0.f;
#pragma unroll 8
    for (int k4 = 0; k4 < 64; k4++) {
        float4 l0 = *(const float4*)&L[r * 256 + k4 * 4];
        float4 l1 = *(const float4*)&L[(r + 1) * 256 + k4 * 4];
#pragma unroll
        for (int j = 0; j < 4; j++) {
            float4 rv = *(const float4*)&R[(c0 + j) * 256 + k4 * 4];
            s[0][j] += l0.x * rv.x + l0.y * rv.y + l0.z * rv.z + l0.w * rv.w;
            s[1][j] += l1.x * rv.x + l1.y * rv.y + l1.z * rv.z + l1.w * rv.w;
        }
    }
    *(float4*)&C[r * 64 + c0] = make_float4(s[0][0], s[0][1], s[0][2], s[0][3]);
    *(float4*)&C[(r + 1) * 64 + c0] = make_float4(s[1][0], s[1][1], s[1][2], s[1][3]);
}

__device__ void dot64_512(const float* __restrict__ A, const float* __restrict__ B,
                          float* __restrict__ C, float* __restrict__ C2, int lt) {
    int r = (lt >> 4) * 2, c0 = (lt & 15) * 4;
    float4 a0 = make_float4(0.f, 0.f, 0.f, 0.f), a1 = a0;
#pragma unroll 8
    for (int k = 0; k < 64; k++) {
        float x0 = A[r * 64 + k], x1 = A[(r + 1) * 64 + k];
        float4 bv = *(const float4*)&B[k * 64 + c0];
        a0.x += x0 * bv.x; a0.y += x0 * bv.y; a0.z += x0 * bv.z; a0.w += x0 * bv.w;
        a1.x += x1 * bv.x; a1.y += x1 * bv.y; a1.z += x1 * bv.z; a1.w += x1 * bv.w;
    }
    *(float4*)&C[r * 64 + c0] = a0;
    *(float4*)&C[(r + 1) * 64 + c0] = a1;
    if (C2) {
        *(float4*)&C2[r * 64 + c0] = a0;
        *(float4*)&C2[(r + 1) * 64 + c0] = a1;
    }
}

// QtP = Qm^T diag(ex) Qm, QtQ = Qm^T Qm, U1 = AAt + LMB*Qm^T diag(ex^2) Qm
__device__ void qt_fused512(const float* __restrict__ ex, int lt) {
    int r = (lt >> 4) * 2, c0 = (lt & 15) * 4;
    float4 p0 = make_float4(0.f, 0.f, 0.f, 0.f), p1 = p0;
    float4 q0 = p0, q1 = p0, u0 = p0, u1 = p0;
    for (int k = 0; k < 64; k++) {
        float a0 = g_Qm[k * 64 + r], a1 = g_Qm[k * 64 + r + 1];
        float e = ex[k];
        float4 qc = *(const float4*)&g_Qm[k * 64 + c0];
        float t0 = a0 * e, t1 = a1 * e, w0 = t0 * e, w1 = t1 * e;
        p0.x += t0 * qc.x; p0.y += t0 * qc.y; p0.z += t0 * qc.z; p0.w += t0 * qc.w;
        p1.x += t1 * qc.x; p1.y += t1 * qc.y; p1.z += t1 * qc.z; p1.w += t1 * qc.w;
        q0.x += a0 * qc.x; q0.y += a0 * qc.y; q0.z += a0 * qc.z; q0.w += a0 * qc.w;
        q1.x += a1 * qc.x; q1.y += a1 * qc.y; q1.z += a1 * qc.z; q1.w += a1 * qc.w;
        u0.x += w0 * qc.x; u0.y += w0 * qc.y; u0.z += w0 * qc.z; u0.w += w0 * qc.w;
        u1.x += w1 * qc.x; u1.y += w1 * qc.y; u1.z += w1 * qc.z; u1.w += w1 * qc.w;
    }
    *(float4*)&g_QtP[r * 64 + c0] = p0;
    *(float4*)&g_QtP[(r + 1) * 64 + c0] = p1;
    *(float4*)&g_QtQ[r * 64 + c0] = q0;
    *(float4*)&g_QtQ[(r + 1) * 64 + c0] = q1;
    float4 v0 = *(const float4*)&g_AAt[r * 64 + c0];
    float4 v1 = *(const float4*)&g_AAt[(r + 1) * 64 + c0];
    *(float4*)&g_U1[r * 64 + c0] =
        make_float4(v0.x + LMB * u0.x, v0.y + LMB * u0.y, v0.z + LMB * u0.z, v0.w + LMB * u0.w);
    *(float4*)&g_U1[(r + 1) * 64 + c0] =
        make_float4(v1.x + LMB * u1.x, v1.y + LMB * u1.y, v1.z + LMB * u1.z, v1.w + LMB * u1.w);
}

// L3 = LMB*Sinv*diag(ey)*S; L4 = L3*diag(ey)
__device__ void l3l4_512(const float* __restrict__ ey, int lt) {
    int r = (lt >> 4) * 2, c0 = (lt & 15) * 4;
    float4 eyc = *(const float4*)&ey[c0];
    float4 a0 = make_float4(0.f, 0.f, 0.f, 0.f), a1 = a0;
    for (int k = 0; k < 64; k++) {
        float w = ey[k];
        float x0 = g_Sinv[r * 64 + k] * w, x1 = g_Sinv[(r + 1) * 64 + k] * w;
        float4 sv = *(const float4*)&g_S[k * 64 + c0];
        a0.x += x0 * sv.x; a0.y += x0 * sv.y; a0.z += x0 * sv.z; a0.w += x0 * sv.w;
        a1.x += x1 * sv.x; a1.y += x1 * sv.y; a1.z += x1 * sv.z; a1.w += x1 * sv.w;
    }
    float4 l30 = make_float4(LMB * a0.x, LMB * a0.y, LMB * a0.z, LMB * a0.w);
    float4 l31 = make_float4(LMB * a1.x, LMB * a1.y, LMB * a1.z, LMB * a1.w);
    *(float4*)&g_L3[r * 64 + c0] = l30;
    *(float4*)&g_L3[(r + 1) * 64 + c0] = l31;
    *(float4*)&g_L4[r * 64 + c0] =
        make_float4(l30.x * eyc.x, l30.y * eyc.y, l30.z * eyc.z, l30.w * eyc.w);
    *(float4*)&g_L4[(r + 1) * 64 + c0] =
        make_float4(l31.x * eyc.x, l31.y * eyc.y, l31.z * eyc.z, l31.w * eyc.w);
}

// 256-thread full 64x64 GEMM: pair = lt>>3 (32), c0 = (lt&7)*8 (two quads)
__device__ void dot64_256(const float* __restrict__ A, const float* __restrict__ B,
                          float* __restrict__ C, int lt) {
    int r = (lt >> 3) * 2, c0 = (lt & 7) * 8;
    float4 a00 = make_float4(0.f, 0.f, 0.f, 0.f), a01 = a00, a10 = a00, a11 = a00;
#pragma unroll 8
    for (int k = 0; k < 64; k++) {
        float x0 = A[r * 64 + k], x1 = A[(r + 1) * 64 + k];
        float4 b0 = *(const float4*)&B[k * 64 + c0];
        float4 b1 = *(const float4*)&B[k * 64 + c0 + 4];
        a00.x += x0 * b0.x; a00.y += x0 * b0.y; a00.z += x0 * b0.z; a00.w += x0 * b0.w;
        a01.x += x0 * b1.x; a01.y += x0 * b1.y; a01.z += x0 * b1.z; a01.w += x0 * b1.w;
        a10.x += x1 * b0.x; a10.y += x1 * b0.y; a10.z += x1 * b0.z; a10.w += x1 * b0.w;
        a11.x += x1 * b1.x; a11.y += x1 * b1.y; a11.z += x1 * b1.z; a11.w += x1 * b1.w;
    }
    *(float4*)&C[r * 64 + c0] = a00;
    *(float4*)&C[r * 64 + c0 + 4] = a01;
    *(float4*)&C[(r + 1) * 64 + c0] = a10;
    *(float4*)&C[(r + 1) * 64 + c0 + 4] = a11;
}

// X update, 1024 threads: r = tid>>4, c0 = (tid&15)*4
__device__ void iterB_1024(int tid, const float* __restrict__ ey, float* __restrict__ out) {
    int r = tid >> 4, c0 = (tid & 15) * 4;
    float eyr = LMB * ey[r];
    float4 xv = *(const float4*)&g_X[r * 64 + c0];
    float4 x0 = *(const float4*)&g_X0[r * 64 + c0];
    float4 m1 = *(const float4*)&g_M1[r * 64 + c0];
    float4 m2 = *(const float4*)&g_M2[r * 64 + c0];
    float4 s = make_float4(xv.x + x0.x - m1.x + eyr * m2.x,
                           xv.y + x0.y - m1.y + eyr * m2.y,
                           xv.z + x0.z - m1.z + eyr * m2.z,
                           xv.w + x0.w - m1.w + eyr * m2.w);
#pragma unroll 8
    for (int k = 0; k < 64; k++) {
        float l3 = g_L3[r * 64 + k], l4 = g_L4[r * 64 + k];
        float4 a = *(const float4*)&g_M2[k * 64 + c0];
        float4 b = *(const float4*)&g_M4[k * 64 + c0];
        s.x += l3 * a.x - l4 * b.x;  s.y += l3 * a.y - l4 * b.y;
        s.z += l3 * a.z - l4 * b.z;  s.w += l3 * a.w - l4 * b.w;
    }
    *(float4*)&g_X[r * 64 + c0] = s;
    if (out) *(float4*)&out[r * 64 + c0] = s;
}

// ---------------------------------------------------------------------------
// Mega kernel: 8-CTA cluster does the reduce; ONE cluster sync; CTAs 1-7 exit;
// CTA0 (1024 threads) finishes everything with __syncthreads / named barriers.
// ---------------------------------------------------------------------------
__global__ void __cluster_dims__(8, 1, 1) __launch_bounds__(1024, 1)
mega(const float* __restrict__ sx, const float* __restrict__ sy,
     const float* __restrict__ ex, const float* __restrict__ ey,
     float* __restrict__ out) {
    int b = blockIdx.x;
    int tid = threadIdx.x;

    __shared__ float s_pr[2][2][128];
    __shared__ float s_fc[2][2][64];

    // P0: reduce split-K partials. CTA b handles (mz=b>>2, ct=b&3), 1024 thr.
    {
        int mz = b >> 2, ct = b & 3;
        float* dst = mz ? g_T : g_A;
        int r = tid >> 4, c = (tid & 15) * 4;
        float4 s = make_float4(0.f, 0.f, 0.f, 0.f);
#pragma unroll 3
        for (int ch = 0; ch < NCH; ch++) {
            float4 v = *(const float4*)&g_part[(((size_t)mz * NCH + ch) * 4 + ct) * 4096 + r * 64 + c];
            s.x += v.x; s.y += v.y; s.z += v.z; s.w += v.w;
        }
        *(float4*)&dst[r * 256 + ct * 64 + c] = s;
        if (b == 0) {   // S = sy^T sy
            float4 a = make_float4(0.f, 0.f, 0.f, 0.f);
            for (int k = 0; k < 64; k++) {
                float s0 = sy[k * 64 + r];
                float4 sc = *(const float4*)&sy[k * 64 + c];
                a.x += s0 * sc.x; a.y += s0 * sc.y; a.z += s0 * sc.z; a.w += s0 * sc.w;
            }
            *(float4*)&g_S[r * 64 + c] = a;
        }
    }

    // One cluster sync: publish A, T (and S) to CTA0.
    asm volatile("fence.acq_rel.cluster;" ::: "memory");
    asm volatile("barrier.cluster.arrive.aligned;" ::: "memory");
    asm volatile("barrier.cluster.wait.aligned;" ::: "memory");
    if (b != 0) return;

    int half = tid >> 9;       // 0: warps 0-15, 1: warps 16-31
    int lt = tid & 511;

    // Ph1: gj(sx) || (AAt, TA)
    if (half == 0) gj_inv512(sx, g_Qm, 1, lt, s_pr[0], s_fc[0]);
    else {
        dot_nt256_512(g_A, g_A, g_AAt, lt);
        dot_nt256_512(g_T, g_A, g_TA, lt);
    }
    __syncthreads();

    // Ph2: gj(S) || gj(AAt)
    if (half == 0) gj_inv512(g_S, g_Sinv, 1, lt, s_pr[0], s_fc[0]);
    else           gj_inv512(g_AAt, g_AAti, 2, lt, s_pr[1], s_fc[1]);
    __syncthreads();

    // Ph3: qt_fused (QtP,QtQ,U1) || (L3/L4, X0 = TA*AAti dup X)
    if (half == 0) qt_fused512(ex, lt);
    else {
        l3l4_512(ey, lt);
        dot64_512(g_TA, g_AAti, g_X0, g_X, lt);
    }
    __syncthreads();

    // Ph4: R1 = U1*AAti, R2 = QtP*AAti, R4 = QtQ*AAti (groups of 256)
    {
        int grp = tid >> 8, l2 = tid & 255;
        if (grp == 0)      dot64_256(g_U1,  g_AAti, g_R1, l2);
        else if (grp == 1) dot64_256(g_QtP, g_AAti, g_R2, l2);
        else if (grp == 2) dot64_256(g_QtQ, g_AAti, g_R4, l2);
    }
    __syncthreads();

    // Richardson iterations
    for (int it = 0; it < NITER; it++) {
        int grp = tid >> 8, l2 = tid & 255;
        if (grp == 0)      dot64_256(g_X, g_R1, g_M1, l2);
        else if (grp == 1) dot64_256(g_X, g_R2, g_M2, l2);
        else if (grp == 2) dot64_256(g_X, g_R4, g_M4, l2);
        __syncthreads();
        iterB_1024(tid, ey, (it == NITER - 1) ? out : 0);
        __syncthreads();
    }
}

// ---------------------------------------------------------------------------
// Launch: graph-capturable, allocation-free, deterministic.  2 nodes.
// ---------------------------------------------------------------------------
extern "C" void kernel_launch(void* const* d_in, const int* in_sizes, int n_in,
                              void* d_out, int out_size) {
    const float *fx = 0, *fy = 0, *ex = 0, *ey = 0, *tx = 0, *ty = 0, *sx = 0, *sy = 0;
    int nFeat = 0, nEval = 0, nEvec = 0, nSq = 0;
    for (int i = 0; i < n_in; i++) {
        const float* p = (const float*)d_in[i];
        int n = in_sizes[i];
        if (n == VDIM * MDIM)    { if (nFeat++ == 0) fx = p; else fy = p; }
        else if (n == 64)        { if (nEval++ == 0) ex = p; else ey = p; }
        else if (n == 64 * VDIM) { if (nEvec++ == 0) tx = p; else ty = p; }
        else if (n == 64 * 64)   { if (nSq++   == 0) sx = p; else sy = p; }
    }

    dim3 gB(NCH, 4, 2);
    big_gemm<<<gB, 256>>>(fx, fy, tx, ty);
    mega<<<8, 1024>>>(sx, sy, ex, ey, (float*)d_out);
}

// round 12
// speedup vs baseline: 2.6135x; 2.6135x over previous
#include <cuda_runtime.h>

#define VDIM 5000
#define MDIM 256
#define NCH 37        // split-K chunks: 37*144 = 5328 >= 5000; 37*4*2=296 blocks = 2/SM
#define CHUNK 144
#define LMB 0.001f

// ---------------------------------------------------------------------------
// Device scratch (allocation-free rule), 16B-aligned
// ---------------------------------------------------------------------------
__device__ __align__(16) float g_part[2 * NCH * 4 * 64 * 64];
__device__ __align__(16) float g_A[64 * 256], g_T[64 * 256];
__device__ __align__(16) float g_S[4096];
__device__ __align__(16) float g_AAt[4096], g_TA[4096];
__device__ __align__(16) float g_Qm[4096], g_Sinv[4096], g_AAti[4096];
__device__ __align__(16) float g_QtP[4096], g_QtQ[4096], g_PtP[4096];
__device__ __align__(16) float g_L3[4096], g_L4[4096];
__device__ __align__(16) float g_R1[4096], g_R2[4096], g_R4[4096];
__device__ __align__(16) float g_X0[4096];
__device__ __align__(16) float g_M1[4096], g_M2[4096], g_M4[4096];

// ---------------------------------------------------------------------------
// Big GEMMs: A = tx[64,V] @ fx[V,256], T = ty @ fy.  4x4 microtile, split-K.
// ---------------------------------------------------------------------------
__global__ void __launch_bounds__(256) big_gemm(
        const float* __restrict__ fx, const float* __restrict__ fy,
        const float* __restrict__ tx, const float* __restrict__ ty) {
    int ch = blockIdx.x, ct = blockIdx.y, mz = blockIdx.z;
    const float* f = mz ? fy : fx;
    const float* t = mz ? ty : tx;

    __shared__ __align__(16) float tsT[16][68];
    __shared__ __align__(16) float fs[16][64];

    int tid = threadIdx.x;
    int r0 = (tid >> 4) * 4;
    int c0 = (tid & 15) * 4;

    float acc[4][4];
#pragma unroll
    for (int i = 0; i < 4; i++)
#pragma unroll
        for (int j = 0; j < 4; j++) acc[i][j] = 0.f;

    int lr = tid >> 2, lkq = (tid & 3) * 4;
    int fkk = tid >> 4, fcb = (tid & 15) * 4;

    int k0 = ch * CHUNK;
    for (int sub = 0; sub < CHUNK / 16; ++sub) {
        int kb = k0 + sub * 16;
#pragma unroll
        for (int q = 0; q < 4; q++) {
            int k = kb + lkq + q;
            tsT[lkq + q][lr] = (k < VDIM) ? t[lr * VDIM + k] : 0.f;
        }
        {
            int k = kb + fkk;
            float4 fv = make_float4(0.f, 0.f, 0.f, 0.f);
            if (k < VDIM) fv = *(const float4*)&f[k * MDIM + ct * 64 + fcb];
            *(float4*)&fs[fkk][fcb] = fv;
        }
        __syncthreads();
#pragma unroll
        for (int kk = 0; kk < 16; kk++) {
            float4 av = *(const float4*)&tsT[kk][r0];
            float4 bv = *(const float4*)&fs[kk][c0];
            float a[4] = {av.x, av.y, av.z, av.w};
            float b[4] = {bv.x, bv.y, bv.z, bv.w};
#pragma unroll
            for (int i = 0; i < 4; i++)
#pragma unroll
                for (int j = 0; j < 4; j++) acc[i][j] += a[i] * b[j];
        }
        __syncthreads();
    }
    size_t base = (((size_t)mz * NCH + ch) * 4 + ct) * 4096;
#pragma unroll
    for (int i = 0; i < 4; i++)
        *(float4*)&g_part[base + (size_t)(r0 + i) * 64 + c0] =
            make_float4(acc[i][0], acc[i][1], acc[i][2], acc[i][3]);
}

// ---------------------------------------------------------------------------
// Cluster phase barrier
// ---------------------------------------------------------------------------
__device__ __forceinline__ void csync() {
    asm volatile("fence.acq_rel.cluster;" ::: "memory");
    asm volatile("barrier.cluster.arrive.aligned;" ::: "memory");
    asm volatile("barrier.cluster.wait.aligned;" ::: "memory");
}

// ---------------------------------------------------------------------------
// Register-resident Gauss-Jordan 64x64 inversion, 256 threads (no pivoting;
// SPD / ~I inputs). Thread (r=tid&63, cg=tid>>6) owns 32 cols of the 64x128
// augmented matrix in registers. Pivot row/col double-buffered in shared ->
// 1 barrier/pivot. Pivot row read via LDS.128. Deferred normalization.
// ---------------------------------------------------------------------------
__device__ __noinline__ void gj_inv(const float* __restrict__ Ain, float* __restrict__ Aout) {
    __shared__ __align__(16) float pr[2][128];
    __shared__ float fc[2][64];
    int tid = threadIdx.x;
    int r = tid & 63, cg = tid >> 6, j0 = cg * 32;
    float a[32];
#pragma unroll
    for (int jj = 0; jj < 32; jj++) {
        int j = j0 + jj;
        a[jj] = (j < 64) ? Ain[r * 64 + j] : ((j - 64 == r) ? 1.f : 0.f);
    }
    if (cg == 0) fc[0][r] = a[0];
    if (r == 0) {
#pragma unroll
        for (int jj = 0; jj < 32; jj++) pr[0][j0 + jj] = a[jj];
    }
    __syncthreads();
    float mydiag = 1.f;
#pragma unroll
    for (int p = 0; p < 64; p++) {
        const int cur = p & 1, nxt = cur ^ 1;
        float apiv = fc[cur][p];
        float scale = __fdividef(fc[cur][r], apiv);
        if (r == p) mydiag = apiv;
        if (r != p) {
            const float4* pv = (const float4*)&pr[cur][j0];
#pragma unroll
            for (int q = 0; q < 8; q++) {
                float4 v = pv[q];
                a[q * 4 + 0] -= scale * v.x;
                a[q * 4 + 1] -= scale * v.y;
                a[q * 4 + 2] -= scale * v.z;
                a[q * 4 + 3] -= scale * v.w;
            }
        }
        if (p < 63) {
            const int q = p + 1;
            if (cg == (q >> 5)) fc[nxt][r] = a[q & 31];   // static under unroll
            if (r == q) {
#pragma unroll
                for (int jj = 0; jj < 32; jj++) pr[nxt][j0 + jj] = a[jj];
            }
        }
        __syncthreads();
    }
    if (cg >= 2) {
        float dinv = 1.f / mydiag;
#pragma unroll
        for (int jj = 0; jj < 32; jj++)
            Aout[r * 64 + (j0 - 64) + jj] = a[jj] * dinv;
    }
}

// ---------------------------------------------------------------------------
// 256-thread helpers over 32-row halves: 2x4 register microtiles
// ---------------------------------------------------------------------------
// C[rb..rb+32) : C[r][c] = sum_k L[r*256+k]*R[c*256+k]  (K=256, NT form)
__device__ void dot_nt256h(const float* __restrict__ L, const float* __restrict__ R,
                           float* __restrict__ C, int rb) {
    int tid = threadIdx.x;
    int r = rb + (tid >> 4) * 2, c0 = (tid & 15) * 4;
    float s[2][4];
#pragma unroll
    for (int i = 0; i < 2; i++)
#pragma unroll
        for (int j = 0; j < 4; j++) s[i][j] = 0.f;
#pragma unroll 8
    for (int k4 = 0; k4 < 64; k4++) {
        float4 l0 = *(const float4*)&L[r * 256 + k4 * 4];
        float4 l1 = *(const float4*)&L[(r + 1) * 256 + k4 * 4];
#pragma unroll
        for (int j = 0; j < 4; j++) {
            float4 rv = *(const float4*)&R[(c0 + j) * 256 + k4 * 4];
            s[0][j] += l0.x * rv.x + l0.y * rv.y + l0.z * rv.z + l0.w * rv.w;
            s[1][j] += l1.x * rv.x + l1.y * rv.y + l1.z * rv.z + l1.w * rv.w;
        }
    }
    *(float4*)&C[r * 64 + c0] = make_float4(s[0][0], s[0][1], s[0][2], s[0][3]);
    *(float4*)&C[(r + 1) * 64 + c0] = make_float4(s[1][0], s[1][1], s[1][2], s[1][3]);
}

// C[rb..rb+32) = scale * A(64x64)*B(64x64)
__device__ void dot64h(const float* __restrict__ A, const float* __restrict__ B,
                       float* __restrict__ C, int rb, float scale) {
    int tid = threadIdx.x;
    int r = rb + (tid >> 4) * 2, c0 = (tid & 15) * 4;
    float4 a0 = make_float4(0.f, 0.f, 0.f, 0.f), a1 = a0;
#pragma unroll 8
    for (int k = 0; k < 64; k++) {
        float x0 = A[r * 64 + k], x1 = A[(r + 1) * 64 + k];
        float4 bv = *(const float4*)&B[k * 64 + c0];
        a0.x += x0 * bv.x; a0.y += x0 * bv.y; a0.z += x0 * bv.z; a0.w += x0 * bv.w;
        a1.x += x1 * bv.x; a1.y += x1 * bv.y; a1.z += x1 * bv.z; a1.w += x1 * bv.w;
    }
    *(float4*)&C[r * 64 + c0] = make_float4(a0.x * scale, a0.y * scale, a0.z * scale, a0.w * scale);
    *(float4*)&C[(r + 1) * 64 + c0] = make_float4(a1.x * scale, a1.y * scale, a1.z * scale, a1.w * scale);
}

// rows rb..rb+32: QtP = Qm^T diag(ex) Qm, QtQ = Qm^T Qm, PtP = Qm^T diag(ex^2) Qm
__device__ void qt_fusedh(const float* __restrict__ ex, int rb) {
    int tid = threadIdx.x;
    int r = rb + (tid >> 4) * 2, c0 = (tid & 15) * 4;
    float4 p0 = make_float4(0.f, 0.f, 0.f, 0.f), p1 = p0;
    float4 q0 = p0, q1 = p0, u0 = p0, u1 = p0;
    for (int k = 0; k < 64; k++) {
        float a0 = g_Qm[k * 64 + r], a1 = g_Qm[k * 64 + r + 1];
        float e = ex[k];
        float4 qc = *(const float4*)&g_Qm[k * 64 + c0];
        float t0 = a0 * e, t1 = a1 * e, w0 = t0 * e, w1 = t1 * e;
        p0.x += t0 * qc.x; p0.y += t0 * qc.y; p0.z += t0 * qc.z; p0.w += t0 * qc.w;
        p1.x += t1 * qc.x; p1.y += t1 * qc.y; p1.z += t1 * qc.z; p1.w += t1 * qc.w;
        q0.x += a0 * qc.x; q0.y += a0 * qc.y; q0.z += a0 * qc.z; q0.w += a0 * qc.w;
        q1.x += a1 * qc.x; q1.y += a1 * qc.y; q1.z += a1 * qc.z; q1.w += a1 * qc.w;
        u0.x += w0 * qc.x; u0.y += w0 * qc.y; u0.z += w0 * qc.z; u0.w += w0 * qc.w;
        u1.x += w1 * qc.x; u1.y += w1 * qc.y; u1.z += w1 * qc.z; u1.w += w1 * qc.w;
    }
    *(float4*)&g_QtP[r * 64 + c0] = p0;
    *(float4*)&g_QtP[(r + 1) * 64 + c0] = p1;
    *(float4*)&g_QtQ[r * 64 + c0] = q0;
    *(float4*)&g_QtQ[(r + 1) * 64 + c0] = q1;
    *(float4*)&g_PtP[r * 64 + c0] = u0;
    *(float4*)&g_PtP[(r + 1) * 64 + c0] = u1;
}

// L3 = LMB*Sinv*diag(ey)*S; L4 = L3*diag(ey)  (full 64 rows, one CTA)
__device__ void l3l4_unit(const float* __restrict__ ey) {
    int tid = threadIdx.x;
    int c0 = (tid & 15) * 4;
    float4 eyc = *(const float4*)&ey[c0];
    for (int h = 0; h < 2; h++) {
        int r = h * 32 + (tid >> 4) * 2;
        float4 a0 = make_float4(0.f, 0.f, 0.f, 0.f), a1 = a0;
        for (int k = 0; k < 64; k++) {
            float w = ey[k];
            float x0 = g_Sinv[r * 64 + k] * w, x1 = g_Sinv[(r + 1) * 64 + k] * w;
            float4 sv = *(const float4*)&g_S[k * 64 + c0];
            a0.x += x0 * sv.x; a0.y += x0 * sv.y; a0.z += x0 * sv.z; a0.w += x0 * sv.w;
            a1.x += x1 * sv.x; a1.y += x1 * sv.y; a1.z += x1 * sv.z; a1.w += x1 * sv.w;
        }
        float4 l30 = make_float4(LMB * a0.x, LMB * a0.y, LMB * a0.z, LMB * a0.w);
        float4 l31 = make_float4(LMB * a1.x, LMB * a1.y, LMB * a1.z, LMB * a1.w);
        *(float4*)&g_L3[r * 64 + c0] = l30;
        *(float4*)&g_L3[(r + 1) * 64 + c0] = l31;
        *(float4*)&g_L4[r * 64 + c0] =
            make_float4(l30.x * eyc.x, l30.y * eyc.y, l30.z * eyc.z, l30.w * eyc.w);
        *(float4*)&g_L4[(r + 1) * 64 + c0] =
            make_float4(l31.x * eyc.x, l31.y * eyc.y, l31.z * eyc.z, l31.w * eyc.w);
    }
}

// S = sy^T sy (full 64 rows, one CTA)
__device__ void computeS(const float* __restrict__ sy) {
    int tid = threadIdx.x;
    int c0 = (tid & 15) * 4;
    for (int h = 0; h < 2; h++) {
        int r = h * 32 + (tid >> 4) * 2;
        float4 a0 = make_float4(0.f, 0.f, 0.f, 0.f), a1 = a0;
        for (int k = 0; k < 64; k++) {
            float s0 = sy[k * 64 + r], s1 = sy[k * 64 + r + 1];
            float4 sc = *(const float4*)&sy[k * 64 + c0];
            a0.x += s0 * sc.x; a0.y += s0 * sc.y; a0.z += s0 * sc.z; a0.w += s0 * sc.w;
            a1.x += s1 * sc.x; a1.y += s1 * sc.y; a1.z += s1 * sc.z; a1.w += s1 * sc.w;
        }
        *(float4*)&g_S[r * 64 + c0] = a0;
        *(float4*)&g_S[(r + 1) * 64 + c0] = a1;
    }
}

// Final combine (16-row slab): out = X0 - M1 + LMB*diag(ey)*M2 + L3*M2 - L4*M4
__device__ void combine_slab(int slab, const float* __restrict__ ey, float* __restrict__ out) {
    int tid = threadIdx.x;
    int r = slab * 16 + (tid >> 4), c0 = (tid & 15) * 4;
    float eyr = LMB * ey[r];
    float4 x0 = *(const float4*)&g_X0[r * 64 + c0];
    float4 m1 = *(const float4*)&g_M1[r * 64 + c0];
    float4 m2 = *(const float4*)&g_M2[r * 64 + c0];
    float4 s = make_float4(x0.x - m1.x + eyr * m2.x,
                           x0.y - m1.y + eyr * m2.y,
                           x0.z - m1.z + eyr * m2.z,
                           x0.w - m1.w + eyr * m2.w);
#pragma unroll 8
    for (int k = 0; k < 64; k++) {
        float l3 = g_L3[r * 64 + k], l4 = g_L4[r * 64 + k];
        float4 a = *(const float4*)&g_M2[k * 64 + c0];
        float4 b = *(const float4*)&g_M4[k * 64 + c0];
        s.x += l3 * a.x - l4 * b.x;  s.y += l3 * a.y - l4 * b.y;
        s.z += l3 * a.z - l4 * b.z;  s.w += l3 * a.w - l4 * b.w;
    }
    *(float4*)&out[r * 64 + c0] = s;
}

// ---------------------------------------------------------------------------
// Mega kernel: 8-CTA cluster, 6 phases.
// ---------------------------------------------------------------------------
__global__ void __cluster_dims__(8, 1, 1) __launch_bounds__(256, 1)
mega(const float* __restrict__ sx, const float* __restrict__ sy,
     const float* __restrict__ ex, const float* __restrict__ ey,
     float* __restrict__ out) {
    int b = blockIdx.x;
    int tid = threadIdx.x;

    // P0: CTA0 gj(sx); CTA1 S + gj(S); CTAs 2..7 reduce 16 half-tile units
    if (b == 0) {
        gj_inv(sx, g_Qm);
    } else if (b == 1) {
        computeS(sy);
        __syncthreads();
        gj_inv(g_S, g_Sinv);
    } else {
        for (int u = b - 2; u < 16; u += 6) {
            int mz = u >> 3, sub = u & 7;
            int ct = sub >> 1, half = sub & 1;
            float* dst = mz ? g_T : g_A;
#pragma unroll
            for (int i = 0; i < 2; i++) {
                int q = tid + i * 256;                 // 512 quads per unit
                int r = half * 32 + (q >> 4), c = (q & 15) * 4;
                float4 s = make_float4(0.f, 0.f, 0.f, 0.f);
#pragma unroll 4
                for (int ch = 0; ch < NCH; ch++) {
                    float4 v = *(const float4*)&g_part[(((size_t)mz * NCH + ch) * 4 + ct) * 4096 + r * 64 + c];
                    s.x += v.x; s.y += v.y; s.z += v.z; s.w += v.w;
                }
                *(float4*)&dst[r * 256 + ct * 64 + c] = s;
            }
        }
    }
    csync();

    // P1: AAt(2) | TA(2) | qt_fused(2) | L3/L4(1)
    if (b < 2)      dot_nt256h(g_A, g_A, g_AAt, b * 32);
    else if (b < 4) dot_nt256h(g_T, g_A, g_TA, (b - 2) * 32);
    else if (b < 6) qt_fusedh(ex, (b - 4) * 32);
    else if (b == 6) l3l4_unit(ey);
    csync();

    // P2: gj(AAt)
    if (b == 0) gj_inv(g_AAt, g_AAti);
    csync();

    // P3: R1' = LMB*PtP*AAti | R2 = QtP*AAti | R4 = QtQ*AAti | X0 = TA*AAti
    if (b < 2)      dot64h(g_PtP, g_AAti, g_R1, b * 32, LMB);
    else if (b < 4) dot64h(g_QtP, g_AAti, g_R2, (b - 2) * 32, 1.f);
    else if (b < 6) dot64h(g_QtQ, g_AAti, g_R4, (b - 4) * 32, 1.f);
    else            dot64h(g_TA, g_AAti, g_X0, (b - 6) * 32, 1.f);
    csync();

    // P4: M1 = X0*R1' | M2 = X0*R2 | M4 = X0*R4
    if (b < 2)      dot64h(g_X0, g_R1, g_M1, b * 32, 1.f);
    else if (b < 4) dot64h(g_X0, g_R2, g_M2, (b - 2) * 32, 1.f);
    else if (b < 6) dot64h(g_X0, g_R4, g_M4, (b - 4) * 32, 1.f);
    csync();

    // P5: combine -> out
    if (b < 4) combine_slab(b, ey, out);
}

// ---------------------------------------------------------------------------
// Launch: graph-capturable, allocation-free, deterministic.  2 nodes.
// ---------------------------------------------------------------------------
extern "C" void kernel_launch(void* const* d_in, const int* in_sizes, int n_in,
                              void* d_out, int out_size) {
    const float *fx = 0, *fy = 0, *ex = 0, *ey = 0, *tx = 0, *ty = 0, *sx = 0, *sy = 0;
    int nFeat = 0, nEval = 0, nEvec = 0, nSq = 0;
    for (int i = 0; i < n_in; i++) {
        const float* p = (const float*)d_in[i];
        int n = in_sizes[i];
        if (n == VDIM * MDIM)    { if (nFeat++ == 0) fx = p; else fy = p; }
        else if (n == 64)        { if (nEval++ == 0) ex = p; else ey = p; }
        else if (n == 64 * VDIM) { if (nEvec++ == 0) tx = p; else ty = p; }
        else if (n == 64 * 64)   { if (nSq++   == 0) sx = p; else sy = p; }
    }

    dim3 gB(NCH, 4, 2);
    big_gemm<<<gB, 256>>>(fx, fy, tx, ty);
    mega<<<8, 256>>>(sx, sy, ex, ey, (float*)d_out);
}